// round 5
// baseline (speedup 1.0000x reference)
#include <cuda_runtime.h>
#include <cuda_bf16.h>

#define FULLMASK 0xffffffffu

static const int B = 64;
static const int S = 512;
static const int T = 16;      // tags
static const int K = 300;     // embed dim
static const int ROWS = B * S;           // 32768
static const int C = 16;      // chunks per sequence
static const int L = 32;      // steps per chunk

// scratch (no allocations allowed -> device globals)
__device__ float g_Mexp[B * C * T * T];   // exp(M - rowmax), row-normalized
__device__ float g_carry[B * C * T];      // per-row log carry

// ============================================================
// Kernel 1: probs[row][j] = sum_k embed[text[row]][k] * W[k][j] + b[j]
// 128 threads/block, 128 rows/block. Register tile TM=4 x TN=4:
// per 4-k step: 8 LDS.128 -> 64 FMA (LDS/FMA balanced).
// ============================================================
static const int PR_ROWS = 128;       // rows per block
static const int KCH = 60;            // k chunk (5 chunks of 60)
static const int EPITCH = 68;         // floats, conflict-free row stride
static const int WPITCH = 316;        // floats (row j base = j*WPITCH + ((j>>2)&3)*4)

__global__ __launch_bounds__(128)
void probs_kernel(const int* __restrict__ text,
                  const float* __restrict__ embed,
                  const float* __restrict__ W,
                  const float* __restrict__ bvec,
                  float* __restrict__ out) {
    __shared__ __align__(16) float Esh[PR_ROWS * EPITCH];   // 34.8 KB
    __shared__ __align__(16) float Wsh[16 * WPITCH];        // 20.2 KB
    __shared__ int tok_sh[PR_ROWS];

    const int tid  = threadIdx.x;        // 0..127
    const int cg   = tid & 3;            // col group: cols cg*4..cg*4+3
    const int rg   = tid >> 2;           // row group: rows rg*4..rg*4+3
    const int wrp  = tid >> 5;           // 0..3
    const int lane = tid & 31;
    const int row0 = blockIdx.x * PR_ROWS;

    // stage W transposed with per-colgroup swizzle: Wsh[j*WPITCH + ((j>>2)&3)*4 + k]
    for (int i = tid; i < K * T; i += 128) {
        int k = i >> 4, j = i & 15;
        Wsh[j * WPITCH + ((j >> 2) & 3) * 4 + k] = W[i];
    }
    tok_sh[tid] = text[row0 + tid];
    __syncthreads();

    // per-thread W base pointers (4 columns)
    const int j0 = cg * 4;
    const float4* Wr0 = (const float4*)(Wsh + (j0 + 0) * WPITCH + cg * 4);
    const float4* Wr1 = (const float4*)(Wsh + (j0 + 1) * WPITCH + cg * 4);
    const float4* Wr2 = (const float4*)(Wsh + (j0 + 2) * WPITCH + cg * 4);
    const float4* Wr3 = (const float4*)(Wsh + (j0 + 3) * WPITCH + cg * 4);

    float acc[4][4];
    #pragma unroll
    for (int m = 0; m < 4; ++m)
        #pragma unroll
        for (int n = 0; n < 4; ++n) acc[m][n] = 0.f;

    float4* Esh4 = (float4*)Esh;   // pitch 17 float4 per row
    const int half = lane >> 4;    // 0/1: which row of the pair
    const int l15  = lane & 15;

    for (int kc = 0; kc < 5; ++kc) {
        const int k0 = kc * KCH;
        // stage 128 rows x 60 floats; each warp: 32 rows, 2 rows/iter
        #pragma unroll
        for (int it = 0; it < 16; ++it) {
            int r = wrp * 32 + it * 2 + half;
            if (l15 < 15) {
                const float4* src = (const float4*)(embed + (size_t)tok_sh[r] * K + k0);
                Esh4[r * 17 + l15] = src[l15];
            }
        }
        __syncthreads();

        const float4* E0 = (const float4*)(Esh + (rg * 4 + 0) * EPITCH);
        const float4* E1 = (const float4*)(Esh + (rg * 4 + 1) * EPITCH);
        const float4* E2 = (const float4*)(Esh + (rg * 4 + 2) * EPITCH);
        const float4* E3 = (const float4*)(Esh + (rg * 4 + 3) * EPITCH);
        const float4* W0 = Wr0 + kc * 15;
        const float4* W1 = Wr1 + kc * 15;
        const float4* W2 = Wr2 + kc * 15;
        const float4* W3 = Wr3 + kc * 15;

        #pragma unroll
        for (int k4 = 0; k4 < 15; ++k4) {
            float4 e[4], w[4];
            e[0] = E0[k4]; e[1] = E1[k4]; e[2] = E2[k4]; e[3] = E3[k4];
            w[0] = W0[k4]; w[1] = W1[k4]; w[2] = W2[k4]; w[3] = W3[k4];
            #pragma unroll
            for (int m = 0; m < 4; ++m) {
                #pragma unroll
                for (int n = 0; n < 4; ++n) {
                    acc[m][n] = fmaf(e[m].x, w[n].x, acc[m][n]);
                    acc[m][n] = fmaf(e[m].y, w[n].y, acc[m][n]);
                    acc[m][n] = fmaf(e[m].z, w[n].z, acc[m][n]);
                    acc[m][n] = fmaf(e[m].w, w[n].w, acc[m][n]);
                }
            }
        }
        __syncthreads();
    }

    float4 bj = *(const float4*)(bvec + j0);
    #pragma unroll
    for (int m = 0; m < 4; ++m) {
        float4 o;
        o.x = acc[m][0] + bj.x;
        o.y = acc[m][1] + bj.y;
        o.z = acc[m][2] + bj.z;
        o.w = acc[m][3] + bj.w;
        *(float4*)(out + (size_t)(row0 + rg * 4 + m) * T + j0) = o;
    }
}

// ============================================================
// Kernel 2: per-(batch, chunk) transfer matrix in LINEAR domain.
// 256 threads = 16 rows x 16 lanes.
// ============================================================
__global__ __launch_bounds__(256, 4)
void chunk_kernel(const int* __restrict__ text,
                  const float* __restrict__ trans,
                  const float* __restrict__ probs) {
    const int c   = blockIdx.x;
    const int b   = blockIdx.y;
    const int tid = threadIdx.x;
    const int j   = tid & 15;
    const int row = tid >> 4;

    __shared__ float tsh[256];
    __shared__ float esh[L * 16];
    __shared__ int   lred[8];

    const float* P  = probs + (size_t)b * S * T;
    const int s0    = 1 + c * L;
    const int send  = min(s0 + L, S);
    const int nload = (send - s0) * 16;

    tsh[tid] = trans[tid];

    // sequence length
    const int* txt = text + b * S;
    int cnt = (txt[tid] != 0 ? 1 : 0) + (txt[tid + 256] != 0 ? 1 : 0);
    #pragma unroll
    for (int off = 16; off; off >>= 1) cnt += __shfl_xor_sync(FULLMASK, cnt, off);
    if ((tid & 31) == 0) lred[tid >> 5] = cnt;

    // stage exp(emit) for this chunk
    #pragma unroll
    for (int it = 0; it < 2; ++it) {
        int i = tid + it * 256;
        esh[i] = (i < nload) ? __expf(P[s0 * 16 + i]) : 1.0f;
    }
    __syncthreads();

    int len = 0;
    #pragma unroll
    for (int wgi = 0; wgi < 8; ++wgi) len += lred[wgi];
    const int lenc = min(len, S);

    float E[16];
    #pragma unroll
    for (int k = 0; k < 16; ++k) E[k] = __expf(tsh[k * 16 + j]);

    float p     = (row == j) ? 1.0f : 0.0f;
    float carry = 0.0f;

    for (int qb = 0; qb < L; qb += 8) {
        #pragma unroll
        for (int q2 = 0; q2 < 8; ++q2) {
            const int q = qb + q2;
            const int s = s0 + q;
            const float em = esh[q * 16 + j];
            float t0 = __shfl_sync(FULLMASK, p, 0, 16)  * E[0];
            float t1 = __shfl_sync(FULLMASK, p, 1, 16)  * E[1];
            float t2 = __shfl_sync(FULLMASK, p, 2, 16)  * E[2];
            float t3 = __shfl_sync(FULLMASK, p, 3, 16)  * E[3];
            t0 = fmaf(__shfl_sync(FULLMASK, p, 4, 16),  E[4],  t0);
            t1 = fmaf(__shfl_sync(FULLMASK, p, 5, 16),  E[5],  t1);
            t2 = fmaf(__shfl_sync(FULLMASK, p, 6, 16),  E[6],  t2);
            t3 = fmaf(__shfl_sync(FULLMASK, p, 7, 16),  E[7],  t3);
            t0 = fmaf(__shfl_sync(FULLMASK, p, 8, 16),  E[8],  t0);
            t1 = fmaf(__shfl_sync(FULLMASK, p, 9, 16),  E[9],  t1);
            t2 = fmaf(__shfl_sync(FULLMASK, p, 10, 16), E[10], t2);
            t3 = fmaf(__shfl_sync(FULLMASK, p, 11, 16), E[11], t3);
            t0 = fmaf(__shfl_sync(FULLMASK, p, 12, 16), E[12], t0);
            t1 = fmaf(__shfl_sync(FULLMASK, p, 13, 16), E[13], t1);
            t2 = fmaf(__shfl_sync(FULLMASK, p, 14, 16), E[14], t2);
            t3 = fmaf(__shfl_sync(FULLMASK, p, 15, 16), E[15], t3);
            float pn = ((t0 + t1) + (t2 + t3)) * em;
            p = (s < lenc) ? pn : p;
        }
        float mx = p;
        mx = fmaxf(mx, __shfl_xor_sync(FULLMASK, mx, 1, 16));
        mx = fmaxf(mx, __shfl_xor_sync(FULLMASK, mx, 2, 16));
        mx = fmaxf(mx, __shfl_xor_sync(FULLMASK, mx, 4, 16));
        mx = fmaxf(mx, __shfl_xor_sync(FULLMASK, mx, 8, 16));
        carry += __logf(mx);
        p *= (1.0f / mx);
    }

    g_Mexp[((b * C + c) * 16 + row) * 16 + j] = p;
    if (j == 0) g_carry[(b * C + c) * 16 + row] = carry;
}

// ============================================================
// Kernel 3: per-batch — len, unary, binary, fold alpha0 through C
// chunk matrices, final logsumexp -> log-likelihood.
// ============================================================
__global__ __launch_bounds__(32, 1)
void combine_kernel(const int* __restrict__ text,
                    const int* __restrict__ tags,
                    const float* __restrict__ trans,
                    const float* __restrict__ probs,
                    float* __restrict__ out_tail) {
    const int b    = blockIdx.x;
    const int lane = threadIdx.x;
    const int j    = lane & 15;

    __shared__ float tsh[256];
    __shared__ float MshT[C * 16 * 16];   // [c][j][i]
    __shared__ float csh[C * 16];
    __shared__ float psh[16];

    for (int i = lane; i < 256; i += 32) tsh[i] = trans[i];
    const float* Mb = g_Mexp + (size_t)b * C * 256;
    for (int i4 = lane; i4 < C * 64; i4 += 32) {
        float4 v4 = ((const float4*)Mb)[i4];
        int i = i4 * 4;
        int cc = i >> 8, r = (i >> 4) & 15, jj = i & 15;
        MshT[cc * 256 + (jj + 0) * 16 + r] = v4.x;
        MshT[cc * 256 + (jj + 1) * 16 + r] = v4.y;
        MshT[cc * 256 + (jj + 2) * 16 + r] = v4.z;
        MshT[cc * 256 + (jj + 3) * 16 + r] = v4.w;
    }
    for (int i = lane; i < C * 16; i += 32) csh[i] = g_carry[b * C * 16 + i];
    __syncwarp();

    const int*   txt = text + b * S;
    const int*   tg  = tags + b * S;
    const float* P   = probs + (size_t)b * S * T;

    // text_lens
    int cnt = 0;
    for (int s = lane; s < S; s += 32) cnt += (txt[s] != 0) ? 1 : 0;
    #pragma unroll
    for (int off = 16; off; off >>= 1) cnt += __shfl_xor_sync(FULLMASK, cnt, off);
    const int len = cnt;

    // unary + binary
    float u = 0.f, bsc = 0.f;
    for (int s = lane; s < S; s += 32) {
        if (s < len) {
            int t = tg[s];
            u += P[s * T + t];
            if (s >= 1) bsc += tsh[tg[s - 1] * T + t];
        }
    }
    #pragma unroll
    for (int off = 16; off; off >>= 1) {
        u   += __shfl_xor_sync(FULLMASK, u, off);
        bsc += __shfl_xor_sync(FULLMASK, bsc, off);
    }

    // fold alpha0 through chunk matrices
    float v = P[j];
    #pragma unroll
    for (int cc = 0; cc < C; ++cc) {
        float w = v + csh[cc * 16 + j];
        float m = w;
        m = fmaxf(m, __shfl_xor_sync(FULLMASK, m, 1, 16));
        m = fmaxf(m, __shfl_xor_sync(FULLMASK, m, 2, 16));
        m = fmaxf(m, __shfl_xor_sync(FULLMASK, m, 4, 16));
        m = fmaxf(m, __shfl_xor_sync(FULLMASK, m, 8, 16));
        float pi = __expf(w - m);
        if (lane < 16) psh[lane] = pi;
        __syncwarp();
        const float4* col = (const float4*)(MshT + cc * 256 + j * 16);
        const float4* pp  = (const float4*)psh;
        float acc = 0.f;
        #pragma unroll
        for (int q = 0; q < 4; ++q) {
            float4 a  = col[q];
            float4 c4 = pp[q];
            acc = fmaf(a.x, c4.x, acc);
            acc = fmaf(a.y, c4.y, acc);
            acc = fmaf(a.z, c4.z, acc);
            acc = fmaf(a.w, c4.w, acc);
        }
        v = __logf(acc) + m;
        __syncwarp();
    }

    // log_norm
    float m = v;
    m = fmaxf(m, __shfl_xor_sync(FULLMASK, m, 1, 16));
    m = fmaxf(m, __shfl_xor_sync(FULLMASK, m, 2, 16));
    m = fmaxf(m, __shfl_xor_sync(FULLMASK, m, 4, 16));
    m = fmaxf(m, __shfl_xor_sync(FULLMASK, m, 8, 16));
    float ex = __expf(v - m);
    ex += __shfl_xor_sync(FULLMASK, ex, 1, 16);
    ex += __shfl_xor_sync(FULLMASK, ex, 2, 16);
    ex += __shfl_xor_sync(FULLMASK, ex, 4, 16);
    ex += __shfl_xor_sync(FULLMASK, ex, 8, 16);
    float logn = m + __logf(ex);

    if (lane == 0) {
        out_tail[b]     = (float)len;
        out_tail[B + b] = u + bsc - logn;
    }
}

// ============================================================
extern "C" void kernel_launch(void* const* d_in, const int* in_sizes, int n_in,
                              void* d_out, int out_size) {
    const int*   text  = (const int*)d_in[0];
    const int*   tags  = (const int*)d_in[1];
    const float* embed = (const float*)d_in[2];
    const float* W     = (const float*)d_in[3];
    const float* bvec  = (const float*)d_in[4];
    const float* trans = (const float*)d_in[5];
    float* out = (float*)d_out;

    probs_kernel<<<ROWS / PR_ROWS, 128>>>(text, embed, W, bvec, out);
    chunk_kernel<<<dim3(C, B), 256>>>(text, trans, out);
    combine_kernel<<<B, 32>>>(text, tags, trans, out, out + (size_t)ROWS * T);
}

// round 10
// speedup vs baseline: 1.0597x; 1.0597x over previous
#include <cuda_runtime.h>
#include <cuda_bf16.h>

#define FULLMASK 0xffffffffu

static const int B = 64;
static const int S = 512;
static const int T = 16;      // tags
static const int K = 300;     // embed dim
static const int ROWS = B * S;           // 32768
static const int C = 16;      // chunks per sequence
static const int L = 32;      // steps per chunk
static const int KS_LEN = 100;           // k per split (3 splits)

// scratch (no allocations allowed -> device globals)
__device__ float g_part[3][ROWS * T];     // probs partials per k-split
__device__ float g_Mexp[B * C * T * T];   // exp(M - rowmax), row-normalized
__device__ float g_carry[B * C * T];      // per-row log carry

// ============================================================
// Kernel 1: partial probs. Block (rb, ks): rows rb*128..+127, k ks*100..+99.
// 128 threads, TM=4 x TN=4. Conflict-free swizzled smem:
//   Esh: per 32-k sub-chunk, f4 slot (k4 + row>>2)&7  -> 8 distinct quads/read
//   Wsh: f4 slot (k4 + 2*(j>>2))&7                    -> 4 distinct quads/read
// ============================================================
static const int PR_ROWS = 128;

__global__ __launch_bounds__(128)
void probs_kernel(const int* __restrict__ text,
                  const float* __restrict__ embed,
                  const float* __restrict__ W,
                  const float* __restrict__ bvec) {
    __shared__ __align__(16) float4 Esh4[128 * 8];   // 16 KB (one 32-k sub-chunk)
    __shared__ __align__(16) float  Wsh[16 * 128];   // 8 KB (100 k, swizzled)
    __shared__ __align__(16) float4 Etl[128];        // tail k 96..99

    const int tid  = threadIdx.x;
    const int rb   = blockIdx.x;
    const int ks   = blockIdx.y;
    const int row0 = rb * PR_ROWS;
    const int cg   = tid & 3;     // col group (4 j)
    const int rg   = tid >> 2;    // row group (4 rows)
    const int k0   = ks * KS_LEN;

    // each thread stages its own row
    const int tok = text[row0 + tid];
    const float4* erow = (const float4*)(embed + (size_t)tok * K + k0);

    float4 buf[8];
    #pragma unroll
    for (int q = 0; q < 8; ++q) buf[q] = erow[q];
    const float4 etl = erow[24];

    // stage W slice [100 k][16 j] transposed + swizzled
    for (int i = tid; i < KS_LEN * 16; i += 128) {
        int k = i >> 4, j = i & 15;
        int k4 = k >> 2, r = k & 3;
        int f4 = (j << 5) + ((k4 >> 3) << 3) + ((k4 + 2 * (j >> 2)) & 7);
        Wsh[(f4 << 2) + r] = W[(k0 + k) * 16 + j];
    }

    float acc[4][4];
    #pragma unroll
    for (int m = 0; m < 4; ++m)
        #pragma unroll
        for (int n = 0; n < 4; ++n) acc[m][n] = 0.f;

    const int j0 = cg * 4;
    const float4* Wsh4 = (const float4*)Wsh;

    #pragma unroll
    for (int sub = 0; sub < 3; ++sub) {
        if (sub) __syncthreads();            // prior compute done (WAR)
        #pragma unroll
        for (int q = 0; q < 8; ++q)
            Esh4[tid * 8 + ((q + rg) & 7)] = buf[q];
        if (sub == 0) Etl[tid] = etl;
        __syncthreads();                     // data ready (covers W/tok on sub 0)

        if (sub < 2) {                       // prefetch next sub-chunk
            const float4* src = erow + (sub + 1) * 8;
            #pragma unroll
            for (int q = 0; q < 8; ++q) buf[q] = src[q];
        }

        #pragma unroll
        for (int q = 0; q < 8; ++q) {
            float4 e[4], w[4];
            #pragma unroll
            for (int m = 0; m < 4; ++m)
                e[m] = Esh4[(rg * 4 + m) * 8 + ((q + rg) & 7)];
            #pragma unroll
            for (int n = 0; n < 4; ++n)
                w[n] = Wsh4[(j0 + n) * 32 + sub * 8 + ((q + 2 * cg) & 7)];
            #pragma unroll
            for (int m = 0; m < 4; ++m)
                #pragma unroll
                for (int n = 0; n < 4; ++n) {
                    acc[m][n] = fmaf(e[m].x, w[n].x, acc[m][n]);
                    acc[m][n] = fmaf(e[m].y, w[n].y, acc[m][n]);
                    acc[m][n] = fmaf(e[m].z, w[n].z, acc[m][n]);
                    acc[m][n] = fmaf(e[m].w, w[n].w, acc[m][n]);
                }
        }
    }

    // tail: k4 global = 24 (k 96..99)
    {
        float4 e[4], w[4];
        #pragma unroll
        for (int m = 0; m < 4; ++m) e[m] = Etl[rg * 4 + m];
        #pragma unroll
        for (int n = 0; n < 4; ++n)
            w[n] = Wsh4[(j0 + n) * 32 + 24 + ((2 * cg) & 7)];
        #pragma unroll
        for (int m = 0; m < 4; ++m)
            #pragma unroll
            for (int n = 0; n < 4; ++n) {
                acc[m][n] = fmaf(e[m].x, w[n].x, acc[m][n]);
                acc[m][n] = fmaf(e[m].y, w[n].y, acc[m][n]);
                acc[m][n] = fmaf(e[m].z, w[n].z, acc[m][n]);
                acc[m][n] = fmaf(e[m].w, w[n].w, acc[m][n]);
            }
    }

    float4 bj = make_float4(0.f, 0.f, 0.f, 0.f);
    if (ks == 0) bj = *(const float4*)(bvec + j0);
    float* dst = g_part[ks];
    #pragma unroll
    for (int m = 0; m < 4; ++m) {
        float4 o;
        o.x = acc[m][0] + bj.x;
        o.y = acc[m][1] + bj.y;
        o.z = acc[m][2] + bj.z;
        o.w = acc[m][3] + bj.w;
        *(float4*)(dst + (size_t)(row0 + rg * 4 + m) * T + j0) = o;
    }
}

// ============================================================
// Kernel 2: per-(batch, chunk) transfer matrix in LINEAR domain.
// Also folds the 3 k-split partials into the final probs output
// (this block's emit rows; chunk c=0 additionally writes row s=0).
// ============================================================
__global__ __launch_bounds__(256, 4)
void chunk_kernel(const int* __restrict__ text,
                  const float* __restrict__ trans,
                  float* __restrict__ probs_out) {
    const int c   = blockIdx.x;
    const int b   = blockIdx.y;
    const int tid = threadIdx.x;
    const int j   = tid & 15;
    const int row = tid >> 4;

    __shared__ float tsh[256];
    __shared__ float esh[L * 16];
    __shared__ int   lred[8];

    const int s0    = 1 + c * L;
    const int send  = min(s0 + L, S);
    const int nload = (send - s0) * 16;
    const int base0 = (b * S + s0) * 16;

    tsh[tid] = trans[tid];

    // sequence length
    const int* txt = text + b * S;
    int cnt = (txt[tid] != 0 ? 1 : 0) + (txt[tid + 256] != 0 ? 1 : 0);
    #pragma unroll
    for (int off = 16; off; off >>= 1) cnt += __shfl_xor_sync(FULLMASK, cnt, off);
    if ((tid & 31) == 0) lred[tid >> 5] = cnt;

    // fold partials -> probs_out, and stage exp(emit)
    const float* p0 = g_part[0] + base0;
    const float* p1 = g_part[1] + base0;
    const float* p2 = g_part[2] + base0;
    float* op = probs_out + base0;
    #pragma unroll
    for (int it = 0; it < 2; ++it) {
        int i = tid + it * 256;
        if (i < nload) {
            float sv = p0[i] + p1[i] + p2[i];
            op[i] = sv;
            esh[i] = __expf(sv);
        } else {
            esh[i] = 1.0f;
        }
    }
    if (c == 0 && tid < 16) {   // row s=0 (alpha0 source, read by combine)
        int bi = b * S * 16 + tid;
        probs_out[bi] = g_part[0][bi] + g_part[1][bi] + g_part[2][bi];
    }
    __syncthreads();

    int len = 0;
    #pragma unroll
    for (int wgi = 0; wgi < 8; ++wgi) len += lred[wgi];
    const int lenc = min(len, S);

    float E[16];
    #pragma unroll
    for (int k = 0; k < 16; ++k) E[k] = __expf(tsh[k * 16 + j]);

    float p     = (row == j) ? 1.0f : 0.0f;
    float carry = 0.0f;

    for (int qb = 0; qb < L; qb += 8) {
        #pragma unroll
        for (int q2 = 0; q2 < 8; ++q2) {
            const int q = qb + q2;
            const int s = s0 + q;
            const float em = esh[q * 16 + j];
            float t0 = __shfl_sync(FULLMASK, p, 0, 16)  * E[0];
            float t1 = __shfl_sync(FULLMASK, p, 1, 16)  * E[1];
            float t2 = __shfl_sync(FULLMASK, p, 2, 16)  * E[2];
            float t3 = __shfl_sync(FULLMASK, p, 3, 16)  * E[3];
            t0 = fmaf(__shfl_sync(FULLMASK, p, 4, 16),  E[4],  t0);
            t1 = fmaf(__shfl_sync(FULLMASK, p, 5, 16),  E[5],  t1);
            t2 = fmaf(__shfl_sync(FULLMASK, p, 6, 16),  E[6],  t2);
            t3 = fmaf(__shfl_sync(FULLMASK, p, 7, 16),  E[7],  t3);
            t0 = fmaf(__shfl_sync(FULLMASK, p, 8, 16),  E[8],  t0);
            t1 = fmaf(__shfl_sync(FULLMASK, p, 9, 16),  E[9],  t1);
            t2 = fmaf(__shfl_sync(FULLMASK, p, 10, 16), E[10], t2);
            t3 = fmaf(__shfl_sync(FULLMASK, p, 11, 16), E[11], t3);
            t0 = fmaf(__shfl_sync(FULLMASK, p, 12, 16), E[12], t0);
            t1 = fmaf(__shfl_sync(FULLMASK, p, 13, 16), E[13], t1);
            t2 = fmaf(__shfl_sync(FULLMASK, p, 14, 16), E[14], t2);
            t3 = fmaf(__shfl_sync(FULLMASK, p, 15, 16), E[15], t3);
            float pn = ((t0 + t1) + (t2 + t3)) * em;
            p = (s < lenc) ? pn : p;
        }
        float mx = p;
        mx = fmaxf(mx, __shfl_xor_sync(FULLMASK, mx, 1, 16));
        mx = fmaxf(mx, __shfl_xor_sync(FULLMASK, mx, 2, 16));
        mx = fmaxf(mx, __shfl_xor_sync(FULLMASK, mx, 4, 16));
        mx = fmaxf(mx, __shfl_xor_sync(FULLMASK, mx, 8, 16));
        carry += __logf(mx);
        p *= (1.0f / mx);
    }

    g_Mexp[((b * C + c) * 16 + row) * 16 + j] = p;
    if (j == 0) g_carry[(b * C + c) * 16 + row] = carry;
}

// ============================================================
// Kernel 3: per-batch — len, unary, binary, fold alpha0 through C
// chunk matrices, final logsumexp -> log-likelihood.
// ============================================================
__global__ __launch_bounds__(32, 1)
void combine_kernel(const int* __restrict__ text,
                    const int* __restrict__ tags,
                    const float* __restrict__ trans,
                    const float* __restrict__ probs,
                    float* __restrict__ out_tail) {
    const int b    = blockIdx.x;
    const int lane = threadIdx.x;
    const int j    = lane & 15;

    __shared__ float tsh[256];
    __shared__ float MshT[C * 16 * 16];   // [c][j][i]
    __shared__ float csh[C * 16];
    __shared__ float psh[16];

    for (int i = lane; i < 256; i += 32) tsh[i] = trans[i];
    const float* Mb = g_Mexp + (size_t)b * C * 256;
    for (int i4 = lane; i4 < C * 64; i4 += 32) {
        float4 v4 = ((const float4*)Mb)[i4];
        int i = i4 * 4;
        int cc = i >> 8, r = (i >> 4) & 15, jj = i & 15;
        MshT[cc * 256 + (jj + 0) * 16 + r] = v4.x;
        MshT[cc * 256 + (jj + 1) * 16 + r] = v4.y;
        MshT[cc * 256 + (jj + 2) * 16 + r] = v4.z;
        MshT[cc * 256 + (jj + 3) * 16 + r] = v4.w;
    }
    for (int i = lane; i < C * 16; i += 32) csh[i] = g_carry[b * C * 16 + i];
    __syncwarp();

    const int*   txt = text + b * S;
    const int*   tg  = tags + b * S;
    const float* P   = probs + (size_t)b * S * T;

    // text_lens
    int cnt = 0;
    for (int s = lane; s < S; s += 32) cnt += (txt[s] != 0) ? 1 : 0;
    #pragma unroll
    for (int off = 16; off; off >>= 1) cnt += __shfl_xor_sync(FULLMASK, cnt, off);
    const int len = cnt;

    // unary + binary
    float u = 0.f, bsc = 0.f;
    for (int s = lane; s < S; s += 32) {
        if (s < len) {
            int t = tg[s];
            u += P[s * T + t];
            if (s >= 1) bsc += tsh[tg[s - 1] * T + t];
        }
    }
    #pragma unroll
    for (int off = 16; off; off >>= 1) {
        u   += __shfl_xor_sync(FULLMASK, u, off);
        bsc += __shfl_xor_sync(FULLMASK, bsc, off);
    }

    // fold alpha0 through chunk matrices
    float v = P[j];
    #pragma unroll
    for (int cc = 0; cc < C; ++cc) {
        float w = v + csh[cc * 16 + j];
        float m = w;
        m = fmaxf(m, __shfl_xor_sync(FULLMASK, m, 1, 16));
        m = fmaxf(m, __shfl_xor_sync(FULLMASK, m, 2, 16));
        m = fmaxf(m, __shfl_xor_sync(FULLMASK, m, 4, 16));
        m = fmaxf(m, __shfl_xor_sync(FULLMASK, m, 8, 16));
        float pi = __expf(w - m);
        if (lane < 16) psh[lane] = pi;
        __syncwarp();
        const float4* col = (const float4*)(MshT + cc * 256 + j * 16);
        const float4* pp  = (const float4*)psh;
        float acc = 0.f;
        #pragma unroll
        for (int q = 0; q < 4; ++q) {
            float4 a  = col[q];
            float4 c4 = pp[q];
            acc = fmaf(a.x, c4.x, acc);
            acc = fmaf(a.y, c4.y, acc);
            acc = fmaf(a.z, c4.z, acc);
            acc = fmaf(a.w, c4.w, acc);
        }
        v = __logf(acc) + m;
        __syncwarp();
    }

    // log_norm
    float m = v;
    m = fmaxf(m, __shfl_xor_sync(FULLMASK, m, 1, 16));
    m = fmaxf(m, __shfl_xor_sync(FULLMASK, m, 2, 16));
    m = fmaxf(m, __shfl_xor_sync(FULLMASK, m, 4, 16));
    m = fmaxf(m, __shfl_xor_sync(FULLMASK, m, 8, 16));
    float ex = __expf(v - m);
    ex += __shfl_xor_sync(FULLMASK, ex, 1, 16);
    ex += __shfl_xor_sync(FULLMASK, ex, 2, 16);
    ex += __shfl_xor_sync(FULLMASK, ex, 4, 16);
    ex += __shfl_xor_sync(FULLMASK, ex, 8, 16);
    float logn = m + __logf(ex);

    if (lane == 0) {
        out_tail[b]     = (float)len;
        out_tail[B + b] = u + bsc - logn;
    }
}

// ============================================================
extern "C" void kernel_launch(void* const* d_in, const int* in_sizes, int n_in,
                              void* d_out, int out_size) {
    const int*   text  = (const int*)d_in[0];
    const int*   tags  = (const int*)d_in[1];
    const float* embed = (const float*)d_in[2];
    const float* W     = (const float*)d_in[3];
    const float* bvec  = (const float*)d_in[4];
    const float* trans = (const float*)d_in[5];
    float* out = (float*)d_out;

    probs_kernel<<<dim3(ROWS / PR_ROWS, 3), 128>>>(text, embed, W, bvec);
    chunk_kernel<<<dim3(C, B), 256>>>(text, trans, out);
    combine_kernel<<<B, 32>>>(text, tags, trans, out, out + (size_t)ROWS * T);
}

// round 12
// speedup vs baseline: 1.4449x; 1.3635x over previous
#include <cuda_runtime.h>
#include <cuda_bf16.h>

#define FULLMASK 0xffffffffu

static const int B = 64;
static const int S = 512;
static const int T = 16;      // tags
static const int K = 300;     // embed dim
static const int ROWS = B * S;           // 32768
static const int C = 16;      // chunks per sequence
static const int L = 32;      // steps per chunk
static const int KS_LEN = 100;           // k per split (3 splits)

// scratch (no allocations allowed -> device globals)
__device__ float g_part[3][ROWS * T];     // probs partials per k-split
__device__ float g_Mexp[B * C * T * T];   // exp(M - rowmax), row-normalized
__device__ float g_carry[B * C * T];      // per-row log carry
__device__ float g_usum[B * C];           // unary partial per chunk
__device__ float g_bsum[B * C];           // binary partial per chunk
__device__ int   g_len[B];                // sequence lengths

// ============================================================
// Kernel 1: partial probs. Block (rb, ks): rows rb*64..+63, k ks*100..+99.
// 128 threads, TM=2 x TN=4. Coalesced cooperative staging; rotation-
// swizzled smem (conflict-free reads).
// ============================================================
static const int PR_ROWS = 64;

__global__ __launch_bounds__(128)
void probs_kernel(const int* __restrict__ text,
                  const float* __restrict__ embed,
                  const float* __restrict__ W,
                  const float* __restrict__ bvec) {
    __shared__ __align__(16) float4 Esh4[PR_ROWS * 24];  // 24 KB (k4 groups 0..2)
    __shared__ __align__(16) float4 Etl[PR_ROWS];        // 1 KB (tail k4=24)
    __shared__ __align__(16) float  Wsh[16 * 128];       // 8 KB (100 k, swizzled)
    __shared__ int tok_sh[PR_ROWS];

    const int tid  = threadIdx.x;
    const int rb   = blockIdx.x;
    const int ks   = blockIdx.y;
    const int row0 = rb * PR_ROWS;
    const int cg   = tid & 3;      // col group (4 j)
    const int rg   = tid >> 2;     // row group (2 rows): 0..31
    const int k0   = ks * KS_LEN;

    if (tid < PR_ROWS) tok_sh[tid] = text[row0 + tid];

    // stage W slice [100 k][16 j] transposed + swizzled
    for (int i = tid; i < KS_LEN * 16; i += 128) {
        int k = i >> 4, j = i & 15;
        int k4 = k >> 2, r = k & 3;
        int f4 = (j << 5) + ((k4 >> 3) << 3) + ((k4 + 2 * (j >> 2)) & 7);
        Wsh[(f4 << 2) + r] = W[(k0 + k) * 16 + j];
    }
    __syncthreads();   // tok_sh ready

    // coalesced staging: 64 rows x 25 float4 (consecutive lanes ->
    // consecutive float4s of the same row)
    for (int idx = tid; idx < PR_ROWS * 25; idx += 128) {
        int row = idx / 25;
        int c   = idx - row * 25;
        const float4* src = (const float4*)(embed + (size_t)tok_sh[row] * K + k0);
        float4 v = src[c];
        if (c == 24) Etl[row] = v;
        else Esh4[row * 24 + ((c >> 3) << 3) + (((c & 7) + (row >> 1)) & 7)] = v;
    }
    __syncthreads();

    float acc[2][4];
    #pragma unroll
    for (int m = 0; m < 2; ++m)
        #pragma unroll
        for (int n = 0; n < 4; ++n) acc[m][n] = 0.f;

    const int j0 = cg * 4;
    const float4* Wsh4 = (const float4*)Wsh;
    const int r0 = rg * 2;

    #pragma unroll
    for (int g = 0; g < 3; ++g) {
        #pragma unroll
        for (int q = 0; q < 8; ++q) {
            const int es = (g << 3) + ((q + rg) & 7);
            float4 e0 = Esh4[(r0 + 0) * 24 + es];
            float4 e1 = Esh4[(r0 + 1) * 24 + es];
            float4 w[4];
            #pragma unroll
            for (int n = 0; n < 4; ++n)
                w[n] = Wsh4[(j0 + n) * 32 + (g << 3) + ((q + 2 * cg) & 7)];
            #pragma unroll
            for (int n = 0; n < 4; ++n) {
                acc[0][n] = fmaf(e0.x, w[n].x, acc[0][n]);
                acc[0][n] = fmaf(e0.y, w[n].y, acc[0][n]);
                acc[0][n] = fmaf(e0.z, w[n].z, acc[0][n]);
                acc[0][n] = fmaf(e0.w, w[n].w, acc[0][n]);
                acc[1][n] = fmaf(e1.x, w[n].x, acc[1][n]);
                acc[1][n] = fmaf(e1.y, w[n].y, acc[1][n]);
                acc[1][n] = fmaf(e1.z, w[n].z, acc[1][n]);
                acc[1][n] = fmaf(e1.w, w[n].w, acc[1][n]);
            }
        }
    }
    // tail k4 = 24
    {
        float4 e0 = Etl[r0], e1 = Etl[r0 + 1];
        float4 w[4];
        #pragma unroll
        for (int n = 0; n < 4; ++n)
            w[n] = Wsh4[(j0 + n) * 32 + 24 + ((2 * cg) & 7)];
        #pragma unroll
        for (int n = 0; n < 4; ++n) {
            acc[0][n] = fmaf(e0.x, w[n].x, acc[0][n]);
            acc[0][n] = fmaf(e0.y, w[n].y, acc[0][n]);
            acc[0][n] = fmaf(e0.z, w[n].z, acc[0][n]);
            acc[0][n] = fmaf(e0.w, w[n].w, acc[0][n]);
            acc[1][n] = fmaf(e1.x, w[n].x, acc[1][n]);
            acc[1][n] = fmaf(e1.y, w[n].y, acc[1][n]);
            acc[1][n] = fmaf(e1.z, w[n].z, acc[1][n]);
            acc[1][n] = fmaf(e1.w, w[n].w, acc[1][n]);
        }
    }

    float4 bj = make_float4(0.f, 0.f, 0.f, 0.f);
    if (ks == 0) bj = *(const float4*)(bvec + j0);
    float* dst = g_part[ks];
    #pragma unroll
    for (int m = 0; m < 2; ++m) {
        float4 o;
        o.x = acc[m][0] + bj.x;
        o.y = acc[m][1] + bj.y;
        o.z = acc[m][2] + bj.z;
        o.w = acc[m][3] + bj.w;
        *(float4*)(dst + (size_t)(row0 + r0 + m) * T + j0) = o;
    }
}

// ============================================================
// Kernel 2: per-(batch, chunk) transfer matrix, linear domain.
// 256 threads = 16 rows x 16 lanes. Scan via smem double-buffered
// row-broadcast (no shfl gather). Also folds k-split partials into
// probs output, and computes unary/binary/len partials (warp 0).
// ============================================================
__global__ __launch_bounds__(256, 4)
void chunk_kernel(const int* __restrict__ text,
                  const int* __restrict__ tags,
                  const float* __restrict__ trans,
                  float* __restrict__ probs_out) {
    const int c   = blockIdx.x;
    const int b   = blockIdx.y;
    const int tid = threadIdx.x;
    const int j   = tid & 15;
    const int row = tid >> 4;

    __shared__ float tsh[256];
    __shared__ float esh[L * 16];
    __shared__ float psh2[2][256];
    __shared__ int   lred[8];

    const int s0     = 1 + c * L;
    const int send   = min(s0 + L, S);
    const int nsteps = send - s0;
    const int nload  = nsteps * 16;
    const int base0  = (b * S + s0) * 16;

    tsh[tid] = trans[tid];

    // sequence length
    const int* txt = text + b * S;
    int cnt = (txt[tid] != 0 ? 1 : 0) + (txt[tid + 256] != 0 ? 1 : 0);
    #pragma unroll
    for (int off = 16; off; off >>= 1) cnt += __shfl_xor_sync(FULLMASK, cnt, off);
    if ((tid & 31) == 0) lred[tid >> 5] = cnt;

    // fold partials -> probs_out, and stage exp(emit)
    const float* p0 = g_part[0] + base0;
    const float* p1 = g_part[1] + base0;
    const float* p2 = g_part[2] + base0;
    float* op = probs_out + base0;
    #pragma unroll
    for (int it = 0; it < 2; ++it) {
        int i = tid + it * 256;
        if (i < nload) {
            float sv = p0[i] + p1[i] + p2[i];
            op[i] = sv;
            esh[i] = __expf(sv);
        } else {
            esh[i] = 1.0f;
        }
    }
    if (c == 0 && tid < 16) {   // row s=0 (alpha0 source)
        int bi = b * S * 16 + tid;
        probs_out[bi] = g_part[0][bi] + g_part[1][bi] + g_part[2][bi];
    }
    __syncthreads();

    int len = 0;
    #pragma unroll
    for (int wgi = 0; wgi < 8; ++wgi) len += lred[wgi];
    const int lenc = min(len, S);

    // warp 0: unary/binary partials for this chunk's s-range
    if (tid < 32) {
        const int* tg = tags + b * S;
        int q = tid;
        int s = s0 + q;
        float uu = 0.f, bb = 0.f;
        if (q < nsteps && s < lenc) {
            int t = tg[s];
            uu = op[q * 16 + t];
            bb = tsh[tg[s - 1] * 16 + t];
        }
        if (c == 0 && tid == 0 && lenc > 0)
            uu += probs_out[b * S * 16 + tg[0]];   // s=0 unary
        #pragma unroll
        for (int off = 16; off; off >>= 1) {
            uu += __shfl_xor_sync(FULLMASK, uu, off);
            bb += __shfl_xor_sync(FULLMASK, bb, off);
        }
        if (tid == 0) {
            g_usum[b * C + c] = uu;
            g_bsum[b * C + c] = bb;
            if (c == 0) g_len[b] = lenc;
        }
    }

    // scan: transfer matrix rows in linear domain
    float E[16];
    #pragma unroll
    for (int k = 0; k < 16; ++k) E[k] = __expf(tsh[k * 16 + j]);

    float p     = (row == j) ? 1.0f : 0.0f;
    float carry = 0.0f;
    int   cur   = 0;
    psh2[0][row * 16 + j] = p;

    for (int qb = 0; qb < L; qb += 8) {
        #pragma unroll
        for (int q2 = 0; q2 < 8; ++q2) {
            const int q = qb + q2;
            const int s = s0 + q;
            __syncwarp();
            const float4* prow = (const float4*)(psh2[cur] + row * 16);
            float4 a0 = prow[0], a1 = prow[1], a2 = prow[2], a3 = prow[3];
            float t0 = a0.x * E[0];
            float t1 = a0.y * E[1];
            float t2 = a0.z * E[2];
            float t3 = a0.w * E[3];
            t0 = fmaf(a1.x, E[4],  t0);
            t1 = fmaf(a1.y, E[5],  t1);
            t2 = fmaf(a1.z, E[6],  t2);
            t3 = fmaf(a1.w, E[7],  t3);
            t0 = fmaf(a2.x, E[8],  t0);
            t1 = fmaf(a2.y, E[9],  t1);
            t2 = fmaf(a2.z, E[10], t2);
            t3 = fmaf(a2.w, E[11], t3);
            t0 = fmaf(a3.x, E[12], t0);
            t1 = fmaf(a3.y, E[13], t1);
            t2 = fmaf(a3.z, E[14], t2);
            t3 = fmaf(a3.w, E[15], t3);
            float pn = ((t0 + t1) + (t2 + t3)) * esh[q * 16 + j];
            p = (s < lenc) ? pn : p;
            cur ^= 1;
            psh2[cur][row * 16 + j] = p;
        }
        // renormalize row by its max; accumulate log in carry
        float mx = p;
        mx = fmaxf(mx, __shfl_xor_sync(FULLMASK, mx, 1, 16));
        mx = fmaxf(mx, __shfl_xor_sync(FULLMASK, mx, 2, 16));
        mx = fmaxf(mx, __shfl_xor_sync(FULLMASK, mx, 4, 16));
        mx = fmaxf(mx, __shfl_xor_sync(FULLMASK, mx, 8, 16));
        carry += __logf(mx);
        p *= (1.0f / mx);
        psh2[cur][row * 16 + j] = p;
    }

    g_Mexp[((b * C + c) * 16 + row) * 16 + j] = p;
    if (j == 0) g_carry[(b * C + c) * 16 + row] = carry;
}

// ============================================================
// Kernel 3: per-batch — sum partials, fold alpha0 through C chunk
// matrices, final logsumexp -> log-likelihood.
// ============================================================
__global__ __launch_bounds__(32, 1)
void combine_kernel(const float* __restrict__ probs,
                    float* __restrict__ out_tail) {
    const int b    = blockIdx.x;
    const int lane = threadIdx.x;
    const int j    = lane & 15;

    __shared__ float Msh[C * 256];   // [c][i][j], straight copy
    __shared__ float csh[C * 16];
    __shared__ float psh[16];

    const float* Mb = g_Mexp + (size_t)b * C * 256;
    for (int i4 = lane; i4 < C * 64; i4 += 32)
        ((float4*)Msh)[i4] = ((const float4*)Mb)[i4];
    for (int i = lane; i < C * 16; i += 32) csh[i] = g_carry[b * C * 16 + i];
    __syncwarp();

    // unary + binary partial sums
    float u = 0.f, bsc = 0.f;
    if (lane < 16) { u = g_usum[b * C + lane]; bsc = g_bsum[b * C + lane]; }
    #pragma unroll
    for (int off = 16; off; off >>= 1) {
        u   += __shfl_xor_sync(FULLMASK, u, off);
        bsc += __shfl_xor_sync(FULLMASK, bsc, off);
    }
    const int len = g_len[b];

    // fold alpha0 through chunk matrices
    float v = probs[(size_t)b * S * T + j];
    #pragma unroll
    for (int cc = 0; cc < C; ++cc) {
        float w = v + csh[cc * 16 + j];
        float m = w;
        m = fmaxf(m, __shfl_xor_sync(FULLMASK, m, 1, 16));
        m = fmaxf(m, __shfl_xor_sync(FULLMASK, m, 2, 16));
        m = fmaxf(m, __shfl_xor_sync(FULLMASK, m, 4, 16));
        m = fmaxf(m, __shfl_xor_sync(FULLMASK, m, 8, 16));
        float pi = __expf(w - m);
        if (lane < 16) psh[lane] = pi;
        __syncwarp();
        float acc = 0.f;
        #pragma unroll
        for (int i = 0; i < 16; ++i)
            acc = fmaf(psh[i], Msh[cc * 256 + i * 16 + j], acc);
        v = __logf(acc) + m;
        __syncwarp();
    }

    // log_norm
    float m = v;
    m = fmaxf(m, __shfl_xor_sync(FULLMASK, m, 1, 16));
    m = fmaxf(m, __shfl_xor_sync(FULLMASK, m, 2, 16));
    m = fmaxf(m, __shfl_xor_sync(FULLMASK, m, 4, 16));
    m = fmaxf(m, __shfl_xor_sync(FULLMASK, m, 8, 16));
    float ex = __expf(v - m);
    ex += __shfl_xor_sync(FULLMASK, ex, 1, 16);
    ex += __shfl_xor_sync(FULLMASK, ex, 2, 16);
    ex += __shfl_xor_sync(FULLMASK, ex, 4, 16);
    ex += __shfl_xor_sync(FULLMASK, ex, 8, 16);
    float logn = m + __logf(ex);

    if (lane == 0) {
        out_tail[b]     = (float)len;
        out_tail[B + b] = u + bsc - logn;
    }
}

// ============================================================
extern "C" void kernel_launch(void* const* d_in, const int* in_sizes, int n_in,
                              void* d_out, int out_size) {
    const int*   text  = (const int*)d_in[0];
    const int*   tags  = (const int*)d_in[1];
    const float* embed = (const float*)d_in[2];
    const float* W     = (const float*)d_in[3];
    const float* bvec  = (const float*)d_in[4];
    const float* trans = (const float*)d_in[5];
    float* out = (float*)d_out;

    probs_kernel<<<dim3(ROWS / PR_ROWS, 3), 128>>>(text, embed, W, bvec);
    chunk_kernel<<<dim3(C, B), 256>>>(text, tags, trans, out);
    combine_kernel<<<B, 32>>>(out, out + (size_t)ROWS * T);
}